// round 5
// baseline (speedup 1.0000x reference)
#include <cuda_runtime.h>
#include <cstddef>
#include <math.h>

#define MEM_DIM 2000
#define FEA 512
#define NTOK 32768          // 32 * 32 * 32 tokens
#define HWN 1024            // 32*32 spatial positions per batch image
#define SHRINK_T 0.0025f
#define EPS_F 1e-12f

// 262 MB global scratch for S / att in token-major [n][m] layout.
__device__ float g_scratch[(size_t)NTOK * MEM_DIM];

// ---------------------------------------------------------------------------
// Accurate expf (Cody-Waite + degree-7 Taylor, ~1 ulp on r<=0), written with
// explicit fmaf so -use_fast_math cannot degrade it.
// ---------------------------------------------------------------------------
__device__ __forceinline__ float exp_acc(float r) {
    float kf = rintf(r * 1.44269504088896341f);
    float f  = fmaf(kf, -0.693359375f, r);            // r - k*ln2_hi (exact)
    f = fmaf(kf, 2.12194440054690583e-4f, f);         // - k*ln2_lo
    float p = 1.9841269841e-4f;                       // 1/5040
    p = fmaf(p, f, 1.3888888889e-3f);                 // 1/720
    p = fmaf(p, f, 8.3333333333e-3f);                 // 1/120
    p = fmaf(p, f, 4.1666666667e-2f);                 // 1/24
    p = fmaf(p, f, 1.6666666667e-1f);                 // 1/6
    p = fmaf(p, f, 0.5f);
    p = fmaf(p, f, 1.0f);
    p = fmaf(p, f, 1.0f);
    int k = (int)kf;                                  // r in [-~10, 0] here
    return p * __int_as_float((127 + k) << 23);
}

// Neumaier compensated accumulate
__device__ __forceinline__ void neum_add(float& s, float& c, float p) {
    float t = s + p;
    float e = (fabsf(s) >= fabsf(p)) ? ((s - t) + p) : ((p - t) + s);
    c += e; s = t;
}

// ---------------------------------------------------------------------------
// K1: S[n][m] = sum_c X[n][c] * W[m][c]   (plain fp32, fmaf accumulate)
// ---------------------------------------------------------------------------
__global__ __launch_bounds__(256) void k1_gemm_scores(
    const float* __restrict__ x, const float* __restrict__ w)
{
    __shared__ float As[16][128];   // [c][token]
    __shared__ float Bs[16][68];    // [c][slot], padded

    const int m0  = blockIdx.x * 64;
    const int n0  = blockIdx.y * 128;
    const int b   = n0 >> 10;
    const int hw0 = n0 & 1023;
    const float* xbase = x + (size_t)b * FEA * HWN + hw0;

    const int tid = threadIdx.x;
    const int tx  = tid & 15;     // slot dim (4 each)
    const int ty  = tid >> 4;     // token dim (8 each)

    float acc[8][4];
#pragma unroll
    for (int i = 0; i < 8; i++)
#pragma unroll
        for (int j = 0; j < 4; j++) acc[i][j] = 0.f;

    for (int c0 = 0; c0 < FEA; c0 += 16) {
#pragma unroll
        for (int it = 0; it < 8; it++) {
            int idx = tid + it * 256;
            int cl = idx >> 7, nl = idx & 127;
            As[cl][nl] = xbase[(size_t)(c0 + cl) * HWN + nl];
        }
#pragma unroll
        for (int it = 0; it < 4; it++) {
            int idx = tid + it * 256;
            int cl = idx & 15, ml = idx >> 4;
            int m = m0 + ml;
            Bs[cl][ml] = (m < MEM_DIM) ? w[(size_t)m * FEA + c0 + cl] : 0.f;
        }
        __syncthreads();

#pragma unroll
        for (int k = 0; k < 16; k++) {
            float a[8], bb[4];
#pragma unroll
            for (int i = 0; i < 8; i++) a[i] = As[k][ty * 8 + i];
#pragma unroll
            for (int j = 0; j < 4; j++) bb[j] = Bs[k][tx * 4 + j];
#pragma unroll
            for (int i = 0; i < 8; i++)
#pragma unroll
                for (int j = 0; j < 4; j++)
                    acc[i][j] = fmaf(a[i], bb[j], acc[i][j]);
        }
        __syncthreads();
    }

    const int m = m0 + tx * 4;
    if (m < MEM_DIM) {  // MEM_DIM % 4 == 0
#pragma unroll
        for (int i = 0; i < 8; i++) {
            int n = n0 + ty * 8 + i;
            float4 v = make_float4(acc[i][0], acc[i][1], acc[i][2], acc[i][3]);
            *reinterpret_cast<float4*>(&g_scratch[(size_t)n * MEM_DIM + m]) = v;
        }
    }
}

// ---------------------------------------------------------------------------
// K2: per-token softmax + hard-shrink + L1 renorm, in-place on g_scratch.
//   Compensated Z / norm sums; near-threshold gates re-decided in fp64 from
//   the raw inputs (truth decision). Needs x, w for the band recompute.
// ---------------------------------------------------------------------------
__global__ __launch_bounds__(256) void k2_softmax_shrink(
    const float* __restrict__ x, const float* __restrict__ w)
{
    __shared__ float red[256];
    __shared__ float redc[256];
    __shared__ double sZd;

    const int n = blockIdx.x;
    float* row = &g_scratch[(size_t)n * MEM_DIM];
    const int tid = threadIdx.x;

    // ---- load + max (exact) ----
    float v[8];
    float lmax = -1e30f;
#pragma unroll
    for (int i = 0; i < 8; i++) {
        int idx = tid + i * 256;
        float t = (idx < MEM_DIM) ? row[idx] : -1e30f;
        v[i] = t;
        lmax = fmaxf(lmax, t);
    }
    red[tid] = lmax; __syncthreads();
    for (int s = 128; s > 0; s >>= 1) {
        if (tid < s) red[tid] = fmaxf(red[tid], red[tid + s]);
        __syncthreads();
    }
    const float rmax = red[0]; __syncthreads();

    // ---- exp + compensated Z ----
    float zs = 0.f, zc = 0.f;
#pragma unroll
    for (int i = 0; i < 8; i++) {
        int idx = tid + i * 256;
        if (idx < MEM_DIM) {
            v[i] = exp_acc(v[i] - rmax);
            neum_add(zs, zc, v[i]);
        }
    }
    red[tid] = zs; redc[tid] = zc; __syncthreads();
    for (int s = 128; s > 0; s >>= 1) {
        if (tid < s) {
            float s1 = red[tid], c1 = redc[tid];
            float s2 = red[tid + s], c2 = redc[tid + s];
            float t = s1 + s2;
            float e = (fabsf(s1) >= fabsf(s2)) ? ((s1 - t) + s2) : ((s2 - t) + s1);
            red[tid] = t; redc[tid] = c1 + c2 + e;
        }
        __syncthreads();
    }
    if (tid == 0) sZd = (double)red[0] + (double)redc[0];
    __syncthreads();
    const double Zd  = sZd;
    const float invZ = (float)(1.0 / Zd);
    __syncthreads();

    // ---- shrink with fp64 band guard ----
    const double Td = (double)SHRINK_T;   // exact fp32 threshold, as double
    float ns = 0.f, nc = 0.f;
#pragma unroll
    for (int i = 0; i < 8; i++) {
        int idx = tid + i * 256;
        if (idx < MEM_DIM) {
            float p = v[i] * invZ;
            float d = p - SHRINK_T;
            bool gate = (d > 0.f);
            if (fabsf(d) < 3e-4f * SHRINK_T) {
                // near-threshold: recompute score & att exactly, decide in fp64
                const float* xr = x + (size_t)(n >> 10) * FEA * HWN + (n & 1023);
                const float* wr = w + (size_t)idx * FEA;
                double s64 = 0.0;
#pragma unroll 4
                for (int cc = 0; cc < FEA; cc++)
                    s64 = fma((double)xr[(size_t)cc * HWN], (double)wr[cc], s64);
                double p64 = exp(s64 - (double)rmax) / Zd;
                gate = (p64 > Td);
            }
            float sh;
            if (gate) sh = (d > 0.f) ? (d * p / (d + EPS_F)) : p;
            else      sh = 0.f;
            v[i] = sh;
            neum_add(ns, nc, sh);
        }
    }

    // ---- compensated L1 norm + renorm ----
    red[tid] = ns; redc[tid] = nc; __syncthreads();
    for (int s = 128; s > 0; s >>= 1) {
        if (tid < s) {
            float s1 = red[tid], c1 = redc[tid];
            float s2 = red[tid + s], c2 = redc[tid + s];
            float t = s1 + s2;
            float e = (fabsf(s1) >= fabsf(s2)) ? ((s1 - t) + s2) : ((s2 - t) + s1);
            red[tid] = t; redc[tid] = c1 + c2 + e;
        }
        __syncthreads();
    }
    const float norm = red[0] + redc[0];
    const float inv  = 1.f / fmaxf(norm, EPS_F);

#pragma unroll
    for (int i = 0; i < 8; i++) {
        int idx = tid + i * 256;
        if (idx < MEM_DIM) row[idx] = v[i] * inv;
    }
}

// ---------------------------------------------------------------------------
// K2b: transpose att from scratch [n][m] to output (B, M, H, W).
// ---------------------------------------------------------------------------
__global__ __launch_bounds__(256) void k2b_transpose_att(float* __restrict__ att_out)
{
    __shared__ float tile[32][33];
    const int m0  = blockIdx.x * 32;
    const int hw0 = blockIdx.y * 32;
    const int b   = blockIdx.z;
    const int tid = threadIdx.x;
    const int cx  = tid & 31;
    const int ry  = tid >> 5;

#pragma unroll
    for (int r = ry; r < 32; r += 8) {
        int m = m0 + cx;
        tile[r][cx] = (m < MEM_DIM)
            ? g_scratch[(size_t)(b * HWN + hw0 + r) * MEM_DIM + m] : 0.f;
    }
    __syncthreads();

#pragma unroll
    for (int c = ry; c < 32; c += 8) {
        int m = m0 + c;
        if (m < MEM_DIM)
            att_out[(size_t)b * MEM_DIM * HWN + (size_t)m * HWN + hw0 + cx] = tile[cx][c];
    }
}

// ---------------------------------------------------------------------------
// K3: Y[n][c] = sum_m A[n][m] * W[m][c]   (plain fp32)
// ---------------------------------------------------------------------------
__global__ __launch_bounds__(256) void k3_gemm_y(
    const float* __restrict__ w, float* __restrict__ y)
{
    __shared__ float As[16][68];    // [m][token], padded
    __shared__ float Bs[16][128];   // [m][c]

    const int c0  = blockIdx.x * 128;
    const int n0  = blockIdx.y * 64;
    const int b   = n0 >> 10;
    const int hw0 = n0 & 1023;

    const int tid = threadIdx.x;
    const int tx  = tid & 15;   // token dim (4 each)
    const int ty  = tid >> 4;   // c dim (8 each)

    float acc[8][4];
#pragma unroll
    for (int i = 0; i < 8; i++)
#pragma unroll
        for (int j = 0; j < 4; j++) acc[i][j] = 0.f;

    for (int m0 = 0; m0 < MEM_DIM; m0 += 16) {
#pragma unroll
        for (int it = 0; it < 4; it++) {
            int idx = tid + it * 256;
            int ml = idx & 15, nl = idx >> 4;
            As[ml][nl] = g_scratch[(size_t)(n0 + nl) * MEM_DIM + m0 + ml];
        }
#pragma unroll
        for (int it = 0; it < 8; it++) {
            int idx = tid + it * 256;
            int cl = idx & 127, ml = idx >> 7;
            Bs[ml][cl] = w[(size_t)(m0 + ml) * FEA + c0 + cl];
        }
        __syncthreads();

#pragma unroll
        for (int k = 0; k < 16; k++) {
            float a[4], bb[8];
#pragma unroll
            for (int j = 0; j < 4; j++) a[j] = As[k][tx * 4 + j];
#pragma unroll
            for (int i = 0; i < 8; i++) bb[i] = Bs[k][ty * 8 + i];
#pragma unroll
            for (int i = 0; i < 8; i++)
#pragma unroll
                for (int j = 0; j < 4; j++)
                    acc[i][j] = fmaf(bb[i], a[j], acc[i][j]);
        }
        __syncthreads();
    }

    float* ybase = y + (size_t)b * FEA * HWN + hw0;
#pragma unroll
    for (int i = 0; i < 8; i++) {
        float4 v = make_float4(acc[i][0], acc[i][1], acc[i][2], acc[i][3]);
        *reinterpret_cast<float4*>(
            &ybase[(size_t)(c0 + ty * 8 + i) * HWN + tx * 4]) = v;
    }
}

// ---------------------------------------------------------------------------
extern "C" void kernel_launch(void* const* d_in, const int* in_sizes, int n_in,
                              void* d_out, int out_size)
{
    const float* x = (const float*)d_in[0];   // (32, 512, 32, 32)
    const float* w = (const float*)d_in[1];   // (2000, 512)
    float* out = (float*)d_out;
    float* y_out   = out;                                  // (32, 512, 32, 32)
    float* att_out = out + (size_t)32 * FEA * HWN;         // (32, 2000, 32, 32)

    {
        dim3 grid((MEM_DIM + 63) / 64, NTOK / 128);
        k1_gemm_scores<<<grid, 256>>>(x, w);
    }
    k2_softmax_shrink<<<NTOK, 256>>>(x, w);
    {
        dim3 grid((MEM_DIM + 31) / 32, HWN / 32, 32);
        k2b_transpose_att<<<grid, 256>>>(att_out);
    }
    {
        dim3 grid(FEA / 128, NTOK / 64);
        k3_gemm_y<<<grid, 256>>>(w, y_out);
    }
}

// round 10
// speedup vs baseline: 1.2329x; 1.2329x over previous
#include <cuda_runtime.h>
#include <cuda_bf16.h>
#include <cstddef>
#include <cstdint>
#include <math.h>

#define MEM_DIM 2000
#define FEA 512
#define NTOK 32768          // 32 * 32 * 32 tokens
#define HWN 1024            // 32*32 spatial positions per batch image
#define SHRINK_T 0.0025f
#define EPS_F 1e-12f

// 262 MB global scratch for S / att in token-major [n][m] layout.
__device__ float g_scratch[(size_t)NTOK * MEM_DIM];

// ===========================================================================
// K1: S[n][m] = sum_c X[n][c] * W[m][c]  — PROVEN R5 fp32 SIMT version.
// ===========================================================================
__global__ __launch_bounds__(256) void k1_gemm_scores(
    const float* __restrict__ x, const float* __restrict__ w)
{
    __shared__ float As[16][128];   // [c][token]
    __shared__ float Bs[16][68];    // [c][slot], padded

    const int m0  = blockIdx.x * 64;
    const int n0  = blockIdx.y * 128;
    const int b   = n0 >> 10;
    const int hw0 = n0 & 1023;
    const float* xbase = x + (size_t)b * FEA * HWN + hw0;

    const int tid = threadIdx.x;
    const int tx  = tid & 15;     // slot dim (4 each)
    const int ty  = tid >> 4;     // token dim (8 each)

    float acc[8][4];
#pragma unroll
    for (int i = 0; i < 8; i++)
#pragma unroll
        for (int j = 0; j < 4; j++) acc[i][j] = 0.f;

    for (int c0 = 0; c0 < FEA; c0 += 16) {
#pragma unroll
        for (int it = 0; it < 8; it++) {
            int idx = tid + it * 256;
            int cl = idx >> 7, nl = idx & 127;
            As[cl][nl] = xbase[(size_t)(c0 + cl) * HWN + nl];
        }
#pragma unroll
        for (int it = 0; it < 4; it++) {
            int idx = tid + it * 256;
            int cl = idx & 15, ml = idx >> 4;
            int m = m0 + ml;
            Bs[cl][ml] = (m < MEM_DIM) ? w[(size_t)m * FEA + c0 + cl] : 0.f;
        }
        __syncthreads();

#pragma unroll
        for (int k = 0; k < 16; k++) {
            float a[8], bb[4];
#pragma unroll
            for (int i = 0; i < 8; i++) a[i] = As[k][ty * 8 + i];
#pragma unroll
            for (int j = 0; j < 4; j++) bb[j] = Bs[k][tx * 4 + j];
#pragma unroll
            for (int i = 0; i < 8; i++)
#pragma unroll
                for (int j = 0; j < 4; j++)
                    acc[i][j] = fmaf(a[i], bb[j], acc[i][j]);
        }
        __syncthreads();
    }

    const int m = m0 + tx * 4;
    if (m < MEM_DIM) {  // MEM_DIM % 4 == 0
#pragma unroll
        for (int i = 0; i < 8; i++) {
            int n = n0 + ty * 8 + i;
            float4 v = make_float4(acc[i][0], acc[i][1], acc[i][2], acc[i][3]);
            *reinterpret_cast<float4*>(&g_scratch[(size_t)n * MEM_DIM + m]) = v;
        }
    }
}

// ===========================================================================
// Warp-level MMA helpers (sm_80-class PTX: valid on compute_103 target)
// ===========================================================================
__device__ __forceinline__ void mma_bf16(float* c, const uint32_t* a, const uint32_t* b) {
    asm volatile(
        "mma.sync.aligned.m16n8k16.row.col.f32.bf16.bf16.f32 "
        "{%0,%1,%2,%3}, {%4,%5,%6,%7}, {%8,%9}, {%0,%1,%2,%3};"
        : "+f"(c[0]), "+f"(c[1]), "+f"(c[2]), "+f"(c[3])
        : "r"(a[0]), "r"(a[1]), "r"(a[2]), "r"(a[3]), "r"(b[0]), "r"(b[1]));
}
__device__ __forceinline__ void ldsm4(uint32_t* r, uint32_t addr) {
    asm volatile("ldmatrix.sync.aligned.m8n8.x4.shared.b16 {%0,%1,%2,%3}, [%4];"
        : "=r"(r[0]), "=r"(r[1]), "=r"(r[2]), "=r"(r[3]) : "r"(addr));
}
__device__ __forceinline__ uint32_t smem_to_u32(const void* p) {
    uint32_t a;
    asm("{ .reg .u64 t; cvta.to.shared.u64 t, %1; cvt.u32.u64 %0, t; }"
        : "=r"(a) : "l"(p));
    return a;
}

// Tile element (row, k) -> swizzled byte offset in a [128][64]-bf16 tile
__device__ __forceinline__ uint32_t sw_off(int row, int k) {
    int chunk = (k >> 3) ^ (row & 7);
    return (uint32_t)(row * 128 + chunk * 16 + (k & 7) * 2);
}

// fp32 -> (hi, lo) bf16 split, packed pairwise.
__device__ __forceinline__ void split2(float v0, float v1, uint32_t& hp, uint32_t& lp) {
    __nv_bfloat16 h0 = __float2bfloat16(v0);
    __nv_bfloat16 h1 = __float2bfloat16(v1);
    __nv_bfloat16 l0 = __float2bfloat16(v0 - __bfloat162float(h0));
    __nv_bfloat16 l1 = __float2bfloat16(v1 - __bfloat162float(h1));
    hp = (uint32_t)__bfloat16_as_ushort(h0) | ((uint32_t)__bfloat16_as_ushort(h1) << 16);
    lp = (uint32_t)__bfloat16_as_ushort(l0) | ((uint32_t)__bfloat16_as_ushort(l1) << 16);
}

// SMEM stage layout: Ah | Al | Bh | Bl, each 16 KB ([128][64] bf16 swizzled)
#define OFF_AH 0
#define OFF_AL 16384
#define OFF_BH 32768
#define OFF_BL 49152
#define STAGE_B 65536

// Per-warp MMA over one staged BK=64 chunk. acc[4][4][4].
__device__ __forceinline__ void mma_chunk(
    uint32_t sb, int wm, int wn, int lid, float acc[4][4][4])
{
    const int m0w = wm * 64;
    const int n0w = wn * 32;
    const int a_row = (lid & 15);
    const int a_kb  = (lid >> 4) << 3;
    const int b_row = ((lid >> 4) << 3) + (lid & 7);
    const int b_kb  = ((lid >> 3) & 1) << 3;

#pragma unroll
    for (int ks = 0; ks < 4; ks++) {
        const int k0 = ks * 16;
        uint32_t Ah[4][4], Al[4][4];
#pragma unroll
        for (int mt = 0; mt < 4; mt++) {
            int row = m0w + mt * 16 + a_row;
            uint32_t o = sw_off(row, k0 + a_kb);
            ldsm4(Ah[mt], sb + OFF_AH + o);
            ldsm4(Al[mt], sb + OFF_AL + o);
        }
#pragma unroll
        for (int ntp = 0; ntp < 2; ntp++) {
            int row = n0w + ntp * 16 + b_row;
            uint32_t o = sw_off(row, k0 + b_kb);
            uint32_t Bh[4], Bl[4];
            ldsm4(Bh, sb + OFF_BH + o);
            ldsm4(Bl, sb + OFF_BL + o);
#pragma unroll
            for (int mt = 0; mt < 4; mt++) {
#pragma unroll
                for (int j = 0; j < 2; j++) {
                    int nt = ntp * 2 + j;
                    mma_bf16(acc[mt][nt], Ah[mt], Bh + 2 * j);
                    mma_bf16(acc[mt][nt], Ah[mt], Bl + 2 * j);
                    mma_bf16(acc[mt][nt], Al[mt], Bh + 2 * j);
                }
            }
        }
    }
}

// ===========================================================================
// K3 (HMMA): Y[n][c] = sum_m A[n][m] * W[m][c], split-bf16 3-pass.
//   CTA tile: 128 tokens (M) x 128 c (N), K=2000 padded to 2048 (32 chunks).
// ===========================================================================
__global__ void __launch_bounds__(256, 2) k3_mma(
    const float* __restrict__ w, float* __restrict__ y)
{
    extern __shared__ char smem[];
    const uint32_t sb = smem_to_u32(smem);
    const int tid = threadIdx.x, wid = tid >> 5, lid = tid & 31;
    const int wm = wid >> 2, wn = wid & 3;

    const int c0t = blockIdx.x * 128;  // c tile
    const int n0  = blockIdx.y * 128;  // token tile
    const int b = n0 >> 10, hw0 = n0 & 1023;

    float acc[4][4][4];
#pragma unroll
    for (int i = 0; i < 4; i++)
#pragma unroll
        for (int j = 0; j < 4; j++)
#pragma unroll
            for (int r = 0; r < 4; r++) acc[i][j][r] = 0.f;

    for (int ch = 0; ch < 32; ch++) {
        const int k0 = ch * 64;
        // ---- stage A (att rows): 128 tok x 32 m-pairs, coalesced along m ----
#pragma unroll 4
        for (int i = 0; i < 16; i++) {
            int p = tid + i * 256;
            int tk = p >> 5, mp = p & 31;
            int mm = k0 + 2 * mp;
            float v0 = 0.f, v1 = 0.f;
            if (mm < MEM_DIM) {
                float2 t = *(const float2*)(g_scratch + (size_t)(n0 + tk) * MEM_DIM + mm);
                v0 = t.x; v1 = t.y;
            }
            uint32_t hp, lp; split2(v0, v1, hp, lp);
            uint32_t o = sw_off(tk, 2 * mp);
            *(uint32_t*)(smem + OFF_AH + o) = hp;
            *(uint32_t*)(smem + OFF_AL + o) = lp;
        }
        // ---- stage B (W^T): 128 c x 32 m-pairs, coalesced along c ----
#pragma unroll 4
        for (int i = 0; i < 16; i++) {
            int p = tid + i * 256;
            int cc = p & 127, mp = p >> 7;
            int mm = k0 + 2 * mp;
            float v0 = 0.f, v1 = 0.f;
            if (mm < MEM_DIM) {
                v0 = w[(size_t)mm * FEA + c0t + cc];
                v1 = w[(size_t)(mm + 1) * FEA + c0t + cc];
            }
            uint32_t hp, lp; split2(v0, v1, hp, lp);
            uint32_t o = sw_off(cc, 2 * mp);
            *(uint32_t*)(smem + OFF_BH + o) = hp;
            *(uint32_t*)(smem + OFF_BL + o) = lp;
        }
        __syncthreads();
        mma_chunk(sb, wm, wn, lid, acc);
        __syncthreads();
    }

    // ---- epilogue: y NCHW ----
    const int g = lid >> 2, tig = lid & 3;
    float* yb = y + (size_t)b * FEA * HWN;
#pragma unroll
    for (int mt = 0; mt < 4; mt++) {
#pragma unroll
        for (int nt = 0; nt < 4; nt++) {
            int hw = hw0 + wm * 64 + mt * 16 + g;
            int c  = c0t + wn * 32 + nt * 8 + tig * 2;
            yb[(size_t)c * HWN + hw]           = acc[mt][nt][0];
            yb[(size_t)(c + 1) * HWN + hw]     = acc[mt][nt][1];
            yb[(size_t)c * HWN + hw + 8]       = acc[mt][nt][2];
            yb[(size_t)(c + 1) * HWN + hw + 8] = acc[mt][nt][3];
        }
    }
}

// ===========================================================================
// Accurate expf + compensated sums (unchanged from passing R5 kernel)
// ===========================================================================
__device__ __forceinline__ float exp_acc(float r) {
    float kf = rintf(r * 1.44269504088896341f);
    float f  = fmaf(kf, -0.693359375f, r);
    f = fmaf(kf, 2.12194440054690583e-4f, f);
    float p = 1.9841269841e-4f;
    p = fmaf(p, f, 1.3888888889e-3f);
    p = fmaf(p, f, 8.3333333333e-3f);
    p = fmaf(p, f, 4.1666666667e-2f);
    p = fmaf(p, f, 1.6666666667e-1f);
    p = fmaf(p, f, 0.5f);
    p = fmaf(p, f, 1.0f);
    p = fmaf(p, f, 1.0f);
    int k = (int)kf;
    return p * __int_as_float((127 + k) << 23);
}
__device__ __forceinline__ void neum_add(float& s, float& c, float p) {
    float t = s + p;
    float e = (fabsf(s) >= fabsf(p)) ? ((s - t) + p) : ((p - t) + s);
    c += e; s = t;
}

// ---------------------------------------------------------------------------
// K2: per-token softmax + hard-shrink + L1 renorm, in-place on g_scratch.
// ---------------------------------------------------------------------------
__global__ __launch_bounds__(256) void k2_softmax_shrink(
    const float* __restrict__ x, const float* __restrict__ w)
{
    __shared__ float red[256];
    __shared__ float redc[256];
    __shared__ double sZd;

    const int n = blockIdx.x;
    float* row = &g_scratch[(size_t)n * MEM_DIM];
    const int tid = threadIdx.x;

    float v[8];
    float lmax = -1e30f;
#pragma unroll
    for (int i = 0; i < 8; i++) {
        int idx = tid + i * 256;
        float t = (idx < MEM_DIM) ? row[idx] : -1e30f;
        v[i] = t;
        lmax = fmaxf(lmax, t);
    }
    red[tid] = lmax; __syncthreads();
    for (int s = 128; s > 0; s >>= 1) {
        if (tid < s) red[tid] = fmaxf(red[tid], red[tid + s]);
        __syncthreads();
    }
    const float rmax = red[0]; __syncthreads();

    float zs = 0.f, zc = 0.f;
#pragma unroll
    for (int i = 0; i < 8; i++) {
        int idx = tid + i * 256;
        if (idx < MEM_DIM) {
            v[i] = exp_acc(v[i] - rmax);
            neum_add(zs, zc, v[i]);
        }
    }
    red[tid] = zs; redc[tid] = zc; __syncthreads();
    for (int s = 128; s > 0; s >>= 1) {
        if (tid < s) {
            float s1 = red[tid], c1 = redc[tid];
            float s2 = red[tid + s], c2 = redc[tid + s];
            float t = s1 + s2;
            float e = (fabsf(s1) >= fabsf(s2)) ? ((s1 - t) + s2) : ((s2 - t) + s1);
            red[tid] = t; redc[tid] = c1 + c2 + e;
        }
        __syncthreads();
    }
    if (tid == 0) sZd = (double)red[0] + (double)redc[0];
    __syncthreads();
    const double Zd  = sZd;
    const float invZ = (float)(1.0 / Zd);
    __syncthreads();

    const double Td = (double)SHRINK_T;
    float ns = 0.f, nc = 0.f;
#pragma unroll
    for (int i = 0; i < 8; i++) {
        int idx = tid + i * 256;
        if (idx < MEM_DIM) {
            float p = v[i] * invZ;
            float d = p - SHRINK_T;
            bool gate = (d > 0.f);
            if (fabsf(d) < 3e-4f * SHRINK_T) {
                const float* xr = x + (size_t)(n >> 10) * FEA * HWN + (n & 1023);
                const float* wr = w + (size_t)idx * FEA;
                double s64 = 0.0;
#pragma unroll 4
                for (int cc = 0; cc < FEA; cc++)
                    s64 = fma((double)xr[(size_t)cc * HWN], (double)wr[cc], s64);
                double p64 = exp(s64 - (double)rmax) / Zd;
                gate = (p64 > Td);
            }
            float sh;
            if (gate) sh = (d > 0.f) ? (d * p / (d + EPS_F)) : p;
            else      sh = 0.f;
            v[i] = sh;
            neum_add(ns, nc, sh);
        }
    }

    red[tid] = ns; redc[tid] = nc; __syncthreads();
    for (int s = 128; s > 0; s >>= 1) {
        if (tid < s) {
            float s1 = red[tid], c1 = redc[tid];
            float s2 = red[tid + s], c2 = redc[tid + s];
            float t = s1 + s2;
            float e = (fabsf(s1) >= fabsf(s2)) ? ((s1 - t) + s2) : ((s2 - t) + s1);
            red[tid] = t; redc[tid] = c1 + c2 + e;
        }
        __syncthreads();
    }
    const float norm = red[0] + redc[0];
    const float inv  = 1.f / fmaxf(norm, EPS_F);

#pragma unroll
    for (int i = 0; i < 8; i++) {
        int idx = tid + i * 256;
        if (idx < MEM_DIM) row[idx] = v[i] * inv;
    }
}

// ---------------------------------------------------------------------------
// K2b: transpose att from scratch [n][m] to output (B, M, H, W).
// ---------------------------------------------------------------------------
__global__ __launch_bounds__(256) void k2b_transpose_att(float* __restrict__ att_out)
{
    __shared__ float tile[32][33];
    const int m0  = blockIdx.x * 32;
    const int hw0 = blockIdx.y * 32;
    const int b   = blockIdx.z;
    const int tid = threadIdx.x;
    const int cx  = tid & 31;
    const int ry  = tid >> 5;

#pragma unroll
    for (int r = ry; r < 32; r += 8) {
        int m = m0 + cx;
        tile[r][cx] = (m < MEM_DIM)
            ? g_scratch[(size_t)(b * HWN + hw0 + r) * MEM_DIM + m] : 0.f;
    }
    __syncthreads();

#pragma unroll
    for (int c = ry; c < 32; c += 8) {
        int m = m0 + c;
        if (m < MEM_DIM)
            att_out[(size_t)b * MEM_DIM * HWN + (size_t)m * HWN + hw0 + cx] = tile[cx][c];
    }
}

// ---------------------------------------------------------------------------
extern "C" void kernel_launch(void* const* d_in, const int* in_sizes, int n_in,
                              void* d_out, int out_size)
{
    const float* x = (const float*)d_in[0];   // (32, 512, 32, 32)
    const float* w = (const float*)d_in[1];   // (2000, 512)
    float* out = (float*)d_out;
    float* y_out   = out;                                  // (32, 512, 32, 32)
    float* att_out = out + (size_t)32 * FEA * HWN;         // (32, 2000, 32, 32)

    cudaFuncSetAttribute(k3_mma, cudaFuncAttributeMaxDynamicSharedMemorySize, STAGE_B);

    {   // K1: scores GEMM -> scratch (fp32 SIMT, proven)
        dim3 grid((MEM_DIM + 63) / 64, NTOK / 128);
        k1_gemm_scores<<<grid, 256>>>(x, w);
    }
    k2_softmax_shrink<<<NTOK, 256>>>(x, w);
    {
        dim3 grid((MEM_DIM + 31) / 32, HWN / 32, 32);
        k2b_transpose_att<<<grid, 256>>>(att_out);
    }
    {   // K3: readout GEMM -> y (HMMA split-bf16, 4 c-tiles x 256 token-tiles)
        dim3 grid(4, 256);
        k3_mma<<<grid, 256, STAGE_B>>>(w, y_out);
    }
}

// round 16
// speedup vs baseline: 1.4179x; 1.1501x over previous
#include <cuda_runtime.h>
#include <cuda_bf16.h>
#include <cstddef>
#include <cstdint>
#include <math.h>

#define MEM_DIM 2000
#define MPAD 2048
#define FEA 512
#define NTOK 32768          // 32 * 32 * 32 tokens
#define HWN 1024            // 32*32 spatial positions per batch image
#define SHRINK_T 0.0025f
#define EPS_F 1e-12f

// Global scratch (static __device__ arrays: sanctioned, no allocations)
__device__ float g_scratch[(size_t)NTOK * MEM_DIM];            // scores / att fp32
__device__ __nv_bfloat16 g_wth[(size_t)FEA * MPAD];            // W^T hi [c][slot], padded
__device__ __nv_bfloat16 g_wtl[(size_t)FEA * MPAD];            // W^T lo
__device__ __nv_bfloat16 g_atth[(size_t)NTOK * MPAD];          // att hi [tok][slot], padded
__device__ __nv_bfloat16 g_attl[(size_t)NTOK * MPAD];          // att lo

// ===========================================================================
// K1: S[n][m] = sum_c X[n][c] * W[m][c] — R5/R10 SIMT numerics (bit-identical
// FMA order), now double-buffered: prefetch next chunk in regs during FMAs.
// ===========================================================================
__global__ __launch_bounds__(256) void k1_gemm_scores(
    const float* __restrict__ x, const float* __restrict__ w)
{
    __shared__ float As[2][16][128];   // [buf][c][token]
    __shared__ float Bs[2][16][68];    // [buf][c][slot], padded

    const int m0  = blockIdx.x * 64;
    const int n0  = blockIdx.y * 128;
    const int b   = n0 >> 10;
    const int hw0 = n0 & 1023;
    const float* xbase = x + (size_t)b * FEA * HWN + hw0;

    const int tid = threadIdx.x;
    const int tx  = tid & 15;     // slot dim (4 each)
    const int ty  = tid >> 4;     // token dim (8 each)

    // load-index precompute (same mapping as R5/R10)
    const int a_cl = tid >> 7;            // base cl for it-th A load: cl = (tid+it*256)>>7 = a_cl + it*2
    const int a_nl = tid & 127;
    const int b_cl = tid & 15;
    const int b_ml0 = tid >> 4;           // ml = b_ml0 + it*16

    float acc[8][4];
#pragma unroll
    for (int i = 0; i < 8; i++)
#pragma unroll
        for (int j = 0; j < 4; j++) acc[i][j] = 0.f;

    float ra[8], rb[4];
    auto ldchunk = [&](int c0) {
#pragma unroll
        for (int it = 0; it < 8; it++) {
            int cl = a_cl + it * 2;
            ra[it] = xbase[(size_t)(c0 + cl) * HWN + a_nl];
        }
#pragma unroll
        for (int it = 0; it < 4; it++) {
            int m = m0 + b_ml0 + it * 16;
            rb[it] = (m < MEM_DIM) ? w[(size_t)m * FEA + c0 + b_cl] : 0.f;
        }
    };
    auto stchunk = [&](int buf) {
#pragma unroll
        for (int it = 0; it < 8; it++)
            As[buf][a_cl + it * 2][a_nl] = ra[it];
#pragma unroll
        for (int it = 0; it < 4; it++)
            Bs[buf][b_cl][b_ml0 + it * 16] = rb[it];
    };

    ldchunk(0);
    stchunk(0);
    __syncthreads();

    for (int ch = 0; ch < FEA / 16; ch++) {
        if (ch + 1 < FEA / 16) ldchunk((ch + 1) * 16);
        const int bs = ch & 1;

#pragma unroll
        for (int k = 0; k < 16; k++) {
            float a[8], bb[4];
#pragma unroll
            for (int i = 0; i < 8; i++) a[i] = As[bs][k][ty * 8 + i];
#pragma unroll
            for (int j = 0; j < 4; j++) bb[j] = Bs[bs][k][tx * 4 + j];
#pragma unroll
            for (int i = 0; i < 8; i++)
#pragma unroll
                for (int j = 0; j < 4; j++)
                    acc[i][j] = fmaf(a[i], bb[j], acc[i][j]);
        }
        if (ch + 1 < FEA / 16) stchunk(bs ^ 1);
        __syncthreads();
    }

    const int m = m0 + tx * 4;
    if (m < MEM_DIM) {  // MEM_DIM % 4 == 0
#pragma unroll
        for (int i = 0; i < 8; i++) {
            int n = n0 + ty * 8 + i;
            float4 v = make_float4(acc[i][0], acc[i][1], acc[i][2], acc[i][3]);
            *reinterpret_cast<float4*>(&g_scratch[(size_t)n * MEM_DIM + m]) = v;
        }
    }
}

// ===========================================================================
// Warp-level MMA helpers (sm_80-class PTX: valid on compute_103 target)
// ===========================================================================
__device__ __forceinline__ void mma_bf16(float* c, const uint32_t* a, const uint32_t* b) {
    asm volatile(
        "mma.sync.aligned.m16n8k16.row.col.f32.bf16.bf16.f32 "
        "{%0,%1,%2,%3}, {%4,%5,%6,%7}, {%8,%9}, {%0,%1,%2,%3};"
        : "+f"(c[0]), "+f"(c[1]), "+f"(c[2]), "+f"(c[3])
        : "r"(a[0]), "r"(a[1]), "r"(a[2]), "r"(a[3]), "r"(b[0]), "r"(b[1]));
}
__device__ __forceinline__ void ldsm4(uint32_t* r, uint32_t addr) {
    asm volatile("ldmatrix.sync.aligned.m8n8.x4.shared.b16 {%0,%1,%2,%3}, [%4];"
        : "=r"(r[0]), "=r"(r[1]), "=r"(r[2]), "=r"(r[3]) : "r"(addr));
}
__device__ __forceinline__ uint32_t smem_to_u32(const void* p) {
    uint32_t a;
    asm("{ .reg .u64 t; cvta.to.shared.u64 t, %1; cvt.u32.u64 %0, t; }"
        : "=r"(a) : "l"(p));
    return a;
}

// Tile element (row, k) -> swizzled byte offset in a [128][64]-bf16 tile
__device__ __forceinline__ uint32_t sw_off(int row, int k) {
    int chunk = (k >> 3) ^ (row & 7);
    return (uint32_t)(row * 128 + chunk * 16 + (k & 7) * 2);
}

// fp32 -> (hi, lo) bf16
__device__ __forceinline__ void split1(float v, __nv_bfloat16& h, __nv_bfloat16& l) {
    h = __float2bfloat16(v);
    l = __float2bfloat16(v - __bfloat162float(h));
}

// SMEM stage layout: Ah | Al | Bh | Bl, each 16 KB ([128][64] bf16 swizzled)
#define OFF_AH 0
#define OFF_AL 16384
#define OFF_BH 32768
#define OFF_BL 49152
#define STAGE_B 65536

// Per-warp MMA over one staged BK=64 chunk. acc[4][4][4]. (PROVEN in K3.)
__device__ __forceinline__ void mma_chunk(
    uint32_t sb, int wm, int wn, int lid, float acc[4][4][4])
{
    const int m0w = wm * 64;
    const int n0w = wn * 32;
    const int a_row = (lid & 15);
    const int a_kb  = (lid >> 4) << 3;
    const int b_row = ((lid >> 4) << 3) + (lid & 7);
    const int b_kb  = ((lid >> 3) & 1) << 3;

#pragma unroll
    for (int ks = 0; ks < 4; ks++) {
        const int k0 = ks * 16;
        uint32_t Ah[4][4], Al[4][4];
#pragma unroll
        for (int mt = 0; mt < 4; mt++) {
            int row = m0w + mt * 16 + a_row;
            uint32_t o = sw_off(row, k0 + a_kb);
            ldsm4(Ah[mt], sb + OFF_AH + o);
            ldsm4(Al[mt], sb + OFF_AL + o);
        }
#pragma unroll
        for (int ntp = 0; ntp < 2; ntp++) {
            int row = n0w + ntp * 16 + b_row;
            uint32_t o = sw_off(row, k0 + b_kb);
            uint32_t Bh[4], Bl[4];
            ldsm4(Bh, sb + OFF_BH + o);
            ldsm4(Bl, sb + OFF_BL + o);
#pragma unroll
            for (int mt = 0; mt < 4; mt++) {
#pragma unroll
                for (int j = 0; j < 2; j++) {
                    int nt = ntp * 2 + j;
                    mma_bf16(acc[mt][nt], Ah[mt], Bh + 2 * j);
                    mma_bf16(acc[mt][nt], Ah[mt], Bl + 2 * j);
                    mma_bf16(acc[mt][nt], Al[mt], Bh + 2 * j);
                }
            }
        }
    }
}

// ===========================================================================
// Prep: split W^T into hi/lo [c][slot], padded to 2048 slots.
// ===========================================================================
__global__ __launch_bounds__(256) void prep_wt(const float* __restrict__ w)
{
    int idx = blockIdx.x * 256 + threadIdx.x;   // 0 .. FEA*MPAD-1
    int c = idx >> 11, m = idx & 2047;
    float v = (m < MEM_DIM) ? w[(size_t)m * FEA + c] : 0.f;
    __nv_bfloat16 h, l; split1(v, h, l);
    g_wth[(size_t)c * MPAD + m] = h;
    g_wtl[(size_t)c * MPAD + m] = l;
}

// ===========================================================================
// K3 (HMMA): Y[n][c] = sum_m A[n][m] * W[m][c].  Pre-split operands:
// A = atth/attl [tok][2048], B = wth/wtl [c][2048]. 32 chunks of 64.
// Value-identical to the R10-passing K3 (same split values, same MMA order).
// ===========================================================================
__global__ void __launch_bounds__(256, 2) k3_mma2(float* __restrict__ y)
{
    extern __shared__ char smem[];
    const uint32_t sb = smem_to_u32(smem);
    const int tid = threadIdx.x, wid = tid >> 5, lid = tid & 31;
    const int wm = wid >> 2, wn = wid & 3;

    const int c0t = blockIdx.x * 128;  // c tile (4)
    const int n0  = blockIdx.y * 128;  // token tile (256)
    const int b = n0 >> 10, hw0 = n0 & 1023;

    float acc[4][4][4];
#pragma unroll
    for (int i = 0; i < 4; i++)
#pragma unroll
        for (int j = 0; j < 4; j++)
#pragma unroll
            for (int r = 0; r < 4; r++) acc[i][j][r] = 0.f;

    for (int ch = 0; ch < 32; ch++) {
        const int k0 = ch * 64;
#pragma unroll
        for (int i = 0; i < 4; i++) {
            int p = tid + i * 256;
            int row = p >> 3, kc = p & 7;
            uint32_t d = (uint32_t)(row * 128 + ((kc ^ (row & 7)) << 4));
            const size_t sa = (size_t)(n0 + row) * MPAD + k0 + kc * 8;
            const size_t sbw = (size_t)(c0t + row) * MPAD + k0 + kc * 8;
            *(uint4*)(smem + OFF_AH + d) = *(const uint4*)(g_atth + sa);
            *(uint4*)(smem + OFF_AL + d) = *(const uint4*)(g_attl + sa);
            *(uint4*)(smem + OFF_BH + d) = *(const uint4*)(g_wth + sbw);
            *(uint4*)(smem + OFF_BL + d) = *(const uint4*)(g_wtl + sbw);
        }
        __syncthreads();
        mma_chunk(sb, wm, wn, lid, acc);
        __syncthreads();
    }

    // ---- epilogue: y NCHW ----
    const int g = lid >> 2, tig = lid & 3;
    float* yb = y + (size_t)b * FEA * HWN;
#pragma unroll
    for (int mt = 0; mt < 4; mt++) {
#pragma unroll
        for (int nt = 0; nt < 4; nt++) {
            int hw = hw0 + wm * 64 + mt * 16 + g;
            int c  = c0t + wn * 32 + nt * 8 + tig * 2;
            yb[(size_t)c * HWN + hw]           = acc[mt][nt][0];
            yb[(size_t)(c + 1) * HWN + hw]     = acc[mt][nt][1];
            yb[(size_t)c * HWN + hw + 8]       = acc[mt][nt][2];
            yb[(size_t)(c + 1) * HWN + hw + 8] = acc[mt][nt][3];
        }
    }
}

// ===========================================================================
// Accurate expf + compensated sums (unchanged from passing kernels)
// ===========================================================================
__device__ __forceinline__ float exp_acc(float r) {
    float kf = rintf(r * 1.44269504088896341f);
    float f  = fmaf(kf, -0.693359375f, r);
    f = fmaf(kf, 2.12194440054690583e-4f, f);
    float p = 1.9841269841e-4f;
    p = fmaf(p, f, 1.3888888889e-3f);
    p = fmaf(p, f, 8.3333333333e-3f);
    p = fmaf(p, f, 4.1666666667e-2f);
    p = fmaf(p, f, 1.6666666667e-1f);
    p = fmaf(p, f, 0.5f);
    p = fmaf(p, f, 1.0f);
    p = fmaf(p, f, 1.0f);
    int k = (int)kf;
    return p * __int_as_float((127 + k) << 23);
}
__device__ __forceinline__ void neum_add(float& s, float& c, float p) {
    float t = s + p;
    float e = (fabsf(s) >= fabsf(p)) ? ((s - t) + p) : ((p - t) + s);
    c += e; s = t;
}

// ---------------------------------------------------------------------------
// K2: per-token softmax + hard-shrink + L1 renorm; writes fp32 scratch (for
// att transpose) AND bf16 hi/lo rows (for K3), zero-padded to 2048.
// Numerics identical to R5/R10 K2.
// ---------------------------------------------------------------------------
__global__ __launch_bounds__(256) void k2_softmax_shrink(
    const float* __restrict__ x, const float* __restrict__ w)
{
    __shared__ float red[256];
    __shared__ float redc[256];
    __shared__ double sZd;

    const int n = blockIdx.x;
    float* row = &g_scratch[(size_t)n * MEM_DIM];
    const int tid = threadIdx.x;

    float v[8];
    float lmax = -1e30f;
#pragma unroll
    for (int i = 0; i < 8; i++) {
        int idx = tid + i * 256;
        float t = (idx < MEM_DIM) ? row[idx] : -1e30f;
        v[i] = t;
        lmax = fmaxf(lmax, t);
    }
    red[tid] = lmax; __syncthreads();
    for (int s = 128; s > 0; s >>= 1) {
        if (tid < s) red[tid] = fmaxf(red[tid], red[tid + s]);
        __syncthreads();
    }
    const float rmax = red[0]; __syncthreads();

    float zs = 0.f, zc = 0.f;
#pragma unroll
    for (int i = 0; i < 8; i++) {
        int idx = tid + i * 256;
        if (idx < MEM_DIM) {
            v[i] = exp_acc(v[i] - rmax);
            neum_add(zs, zc, v[i]);
        }
    }
    red[tid] = zs; redc[tid] = zc; __syncthreads();
    for (int s = 128; s > 0; s >>= 1) {
        if (tid < s) {
            float s1 = red[tid], c1 = redc[tid];
            float s2 = red[tid + s], c2 = redc[tid + s];
            float t = s1 + s2;
            float e = (fabsf(s1) >= fabsf(s2)) ? ((s1 - t) + s2) : ((s2 - t) + s1);
            red[tid] = t; redc[tid] = c1 + c2 + e;
        }
        __syncthreads();
    }
    if (tid == 0) sZd = (double)red[0] + (double)redc[0];
    __syncthreads();
    const double Zd  = sZd;
    const float invZ = (float)(1.0 / Zd);
    __syncthreads();

    const double Td = (double)SHRINK_T;
    float ns = 0.f, nc = 0.f;
#pragma unroll
    for (int i = 0; i < 8; i++) {
        int idx = tid + i * 256;
        if (idx < MEM_DIM) {
            float p = v[i] * invZ;
            float d = p - SHRINK_T;
            bool gate = (d > 0.f);
            if (fabsf(d) < 3e-4f * SHRINK_T) {
                const float* xr = x + (size_t)(n >> 10) * FEA * HWN + (n & 1023);
                const float* wr = w + (size_t)idx * FEA;
                double s64 = 0.0;
#pragma unroll 4
                for (int cc = 0; cc < FEA; cc++)
                    s64 = fma((double)xr[(size_t)cc * HWN], (double)wr[cc], s64);
                double p64 = exp(s64 - (double)rmax) / Zd;
                gate = (p64 > Td);
            }
            float sh;
            if (gate) sh = (d > 0.f) ? (d * p / (d + EPS_F)) : p;
            else      sh = 0.f;
            v[i] = sh;
            neum_add(ns, nc, sh);
        }
    }

    red[tid] = ns; redc[tid] = nc; __syncthreads();
    for (int s = 128; s > 0; s >>= 1) {
        if (tid < s) {
            float s1 = red[tid], c1 = redc[tid];
            float s2 = red[tid + s], c2 = redc[tid + s];
            float t = s1 + s2;
            float e = (fabsf(s1) >= fabsf(s2)) ? ((s1 - t) + s2) : ((s2 - t) + s1);
            red[tid] = t; redc[tid] = c1 + c2 + e;
        }
        __syncthreads();
    }
    const float norm = red[0] + redc[0];
    const float inv  = 1.f / fmaxf(norm, EPS_F);

#pragma unroll
    for (int i = 0; i < 8; i++) {
        int idx = tid + i * 256;           // covers exactly 0..2047
        float val = (idx < MEM_DIM) ? v[i] * inv : 0.f;
        if (idx < MEM_DIM) row[idx] = val;
        __nv_bfloat16 h, l; split1(val, h, l);
        g_atth[(size_t)n * MPAD + idx] = h;
        g_attl[(size_t)n * MPAD + idx] = l;
    }
}

// ---------------------------------------------------------------------------
// K2b: transpose att from scratch [n][m] to output (B, M, H, W).
// ---------------------------------------------------------------------------
__global__ __launch_bounds__(256) void k2b_transpose_att(float* __restrict__ att_out)
{
    __shared__ float tile[32][33];
    const int m0  = blockIdx.x * 32;
    const int hw0 = blockIdx.y * 32;
    const int b   = blockIdx.z;
    const int tid = threadIdx.x;
    const int cx  = tid & 31;
    const int ry  = tid >> 5;

#pragma unroll
    for (int r = ry; r < 32; r += 8) {
        int m = m0 + cx;
        tile[r][cx] = (m < MEM_DIM)
            ? g_scratch[(size_t)(b * HWN + hw0 + r) * MEM_DIM + m] : 0.f;
    }
    __syncthreads();

#pragma unroll
    for (int c = ry; c < 32; c += 8) {
        int m = m0 + c;
        if (m < MEM_DIM)
            att_out[(size_t)b * MEM_DIM * HWN + (size_t)m * HWN + hw0 + cx] = tile[cx][c];
    }
}

// ---------------------------------------------------------------------------
extern "C" void kernel_launch(void* const* d_in, const int* in_sizes, int n_in,
                              void* d_out, int out_size)
{
    const float* x = (const float*)d_in[0];   // (32, 512, 32, 32)
    const float* w = (const float*)d_in[1];   // (2000, 512)
    float* out = (float*)d_out;
    float* y_out   = out;                                  // (32, 512, 32, 32)
    float* att_out = out + (size_t)32 * FEA * HWN;         // (32, 2000, 32, 32)

    cudaFuncSetAttribute(k3_mma2, cudaFuncAttributeMaxDynamicSharedMemorySize, STAGE_B);

    prep_wt<<<(FEA * MPAD) / 256, 256>>>(w);
    {   // K1: scores GEMM -> scratch (SIMT fp32, bit-identical order, double-buffered)
        dim3 grid((MEM_DIM + 63) / 64, NTOK / 128);
        k1_gemm_scores<<<grid, 256>>>(x, w);
    }
    k2_softmax_shrink<<<NTOK, 256>>>(x, w);
    {
        dim3 grid((MEM_DIM + 31) / 32, HWN / 32, 32);
        k2b_transpose_att<<<grid, 256>>>(att_out);
    }
    {   // K3: readout GEMM -> y (HMMA, pre-split operands)
        dim3 grid(FEA / 128, NTOK / 128);
        k3_mma2<<<grid, 256, STAGE_B>>>(y_out);
    }
}